// round 17
// baseline (speedup 1.0000x reference)
#include <cuda_runtime.h>
#include <cuda_bf16.h>
#include <cstdint>

// Problem constants (from reference): B=16, V=4096, E=768
#define BB 16
#define VV 4096
#define EE 768

// out[b,v,e] = seq[b,v,0]*flux_w[v,e] + flux_b[v,e]
//            + seq[b,v,2]*time_w[v,e] + time_b[v,e]
//            + (e even ? sin : cos)( seq[b,v,1] * exp(-e_even*ln(10000)/E) )
//
// R15: STG.256 experiment — the last untested axis. Plain 128-bit loads
// (proven path, NO cache hints: .cs/.evict_last both regressed), but the
// store is one plain 256-bit st.global.v4.b64 per thread per b-iter
// (32 B = full DRAM sector per store op; half the STG count of R3).
// 96 threads/block, thread owns 8 consecutive e; grid = 4096 (one block
// per v — the scheduling shape that wins). This also cleanly A/Bs R7:
// same 8e/thread shape, hint removed.

__device__ __forceinline__ void stg256(float* p, const float4& a, const float4& b) {
    uint64_t x0 = ((uint64_t)__float_as_uint(a.y) << 32) | __float_as_uint(a.x);
    uint64_t x1 = ((uint64_t)__float_as_uint(a.w) << 32) | __float_as_uint(a.z);
    uint64_t x2 = ((uint64_t)__float_as_uint(b.y) << 32) | __float_as_uint(b.x);
    uint64_t x3 = ((uint64_t)__float_as_uint(b.w) << 32) | __float_as_uint(b.z);
    asm volatile("st.global.v4.b64 [%0], {%1,%2,%3,%4};"
                 :: "l"(p), "l"(x0), "l"(x1), "l"(x2), "l"(x3) : "memory");
}

__global__ __launch_bounds__(96) void bert_embed_kernel(
    const float* __restrict__ seq,   // [B, V, 3]
    const float* __restrict__ fw,    // [V, E]
    const float* __restrict__ fb,    // [V, E]
    const float* __restrict__ tw,    // [V, E]
    const float* __restrict__ tb,    // [V, E]
    float* __restrict__ out)         // [B, V, E]
{
    const int v = blockIdx.x;
    const int e = threadIdx.x * 8;            // thread owns e..e+7 (32B-aligned)
    const size_t base = (size_t)v * EE + e;

    // Compulsory weight reads: plain LDG.128 x8, register-resident.
    const float4 wf0 = *reinterpret_cast<const float4*>(fw + base);
    const float4 wf1 = *reinterpret_cast<const float4*>(fw + base + 4);
    const float4 bf0 = *reinterpret_cast<const float4*>(fb + base);
    const float4 bf1 = *reinterpret_cast<const float4*>(fb + base + 4);
    const float4 wt0 = *reinterpret_cast<const float4*>(tw + base);
    const float4 wt1 = *reinterpret_cast<const float4*>(tw + base + 4);
    const float4 bt0 = *reinterpret_cast<const float4*>(tb + base);
    const float4 bt1 = *reinterpret_cast<const float4*>(tb + base + 4);

    // Combined biases.
    const float4 bs0 = make_float4(bf0.x + bt0.x, bf0.y + bt0.y,
                                   bf0.z + bt0.z, bf0.w + bt0.w);
    const float4 bs1 = make_float4(bf1.x + bt1.x, bf1.y + bt1.y,
                                   bf1.z + bt1.z, bf1.w + bt1.w);

    // div_term[i] = exp(2i * (-ln(10000)/E)); 2i = e, e+2, e+4, e+6.
    const float c  = -9.210340371976184f / (float)EE;   // -ln(10000)/E
    const float d0 = __expf((float)(e + 0) * c);
    const float d1 = __expf((float)(e + 2) * c);
    const float d2 = __expf((float)(e + 4) * c);
    const float d3 = __expf((float)(e + 6) * c);

    #pragma unroll
    for (int b = 0; b < BB; b++) {
        const float* s = seq + ((size_t)b * VV + v) * 3;
        const float s0 = __ldg(s + 0);   // flux (broadcast across block)
        const float s1 = __ldg(s + 1);   // passend
        const float s2 = __ldg(s + 2);   // time

        float sn0, cs0, sn1, cs1, sn2, cs2, sn3, cs3;
        __sincosf(s1 * d0, &sn0, &cs0);
        __sincosf(s1 * d1, &sn1, &cs1);
        __sincosf(s1 * d2, &sn2, &cs2);
        __sincosf(s1 * d3, &sn3, &cs3);

        float4 o0, o1;
        o0.x = fmaf(s0, wf0.x, fmaf(s2, wt0.x, bs0.x)) + sn0;
        o0.y = fmaf(s0, wf0.y, fmaf(s2, wt0.y, bs0.y)) + cs0;
        o0.z = fmaf(s0, wf0.z, fmaf(s2, wt0.z, bs0.z)) + sn1;
        o0.w = fmaf(s0, wf0.w, fmaf(s2, wt0.w, bs0.w)) + cs1;
        o1.x = fmaf(s0, wf1.x, fmaf(s2, wt1.x, bs1.x)) + sn2;
        o1.y = fmaf(s0, wf1.y, fmaf(s2, wt1.y, bs1.y)) + cs2;
        o1.z = fmaf(s0, wf1.z, fmaf(s2, wt1.z, bs1.z)) + sn3;
        o1.w = fmaf(s0, wf1.w, fmaf(s2, wt1.w, bs1.w)) + cs3;

        // One plain 256-bit store: full 32B sector per op.
        stg256(out + (size_t)b * (VV * EE) + base, o0, o1);
    }
}

extern "C" void kernel_launch(void* const* d_in, const int* in_sizes, int n_in,
                              void* d_out, int out_size)
{
    const float* seq = (const float*)d_in[0];  // sequence [B,V,3]
    const float* fw  = (const float*)d_in[1];  // flux_w   [V,E]
    const float* fb  = (const float*)d_in[2];  // flux_b   [V,E]
    const float* tw  = (const float*)d_in[3];  // time_w   [V,E]
    const float* tb  = (const float*)d_in[4];  // time_b   [V,E]
    float* out = (float*)d_out;                // [B,V,E]

    dim3 grid(VV);
    dim3 block(EE / 8);  // 96 threads
    bert_embed_kernel<<<grid, block>>>(seq, fw, fb, tw, tb, out);
}